// round 2
// baseline (speedup 1.0000x reference)
#include <cuda_runtime.h>
#include <cuda_bf16.h>
#include <cstdint>
#include <math.h>

// ---------------------------------------------------------------------------
// SimpleModelQ collapsed:
//   qk[b,f]   = (M @ archi[b] + c)[f] / sqrt(258),  M = kW^T qW, c = kW^T qb
//   (q.kb term is constant per batch -> cancels in softmax; kb unused)
//   score[b,s]= qk[b] . feats[b,s]
//   fbar[b]   = softmax-weighted mean of feats  (255-dim)
//   res = vW@fbar+vb; h1=relu(W1@res+b1); h2=relu(W2@h1+b2); out=W3@h2+b3
// ---------------------------------------------------------------------------

#define B_     128
#define S_     1024
#define LAST_  258
#define FEAT_  255

// ---- device scratch (zero-init at load; rows beyond FEAT_ stay zero) ----
__device__ float g_qkp8[8 * 256 * 4];   // per-h-chunk partials [blk][f][{M0,M1,M2,c}]
__device__ float g_fbarT[256 * 128];    // k-major [f][b]; row 255 stays 0 (pad)
__device__ float g_resT[1024 * 128];
__device__ float g_h1T[512 * 128];
__device__ float g_h2T[256 * 128];
__device__ float g_P[4096 * 128];       // split-K partials

// ===========================================================================
// K0: partial M/c over a 128-h chunk. grid 8, block 256 (thread = feature f).
// kW reads coalesced across f; qW/qb staged in smem.
// ===========================================================================
__global__ void __launch_bounds__(256)
k0_kernel(const float* __restrict__ kW, const float* __restrict__ qW,
          const float* __restrict__ qb) {
    __shared__ float sw[128 * 4];
    const int f = threadIdx.x;
    const int h0 = blockIdx.x * 128;
    for (int j = f; j < 512; j += 256) {
        int h = h0 + (j >> 2), k = j & 3;
        sw[j] = (k < 3) ? qW[h * 3 + k] : qb[h];
    }
    __syncthreads();
    float m0 = 0.f, m1 = 0.f, m2 = 0.f, cc = 0.f;
    if (f < FEAT_) {
#pragma unroll 4
        for (int i = 0; i < 128; i++) {
            float kv = kW[(size_t)(h0 + i) * FEAT_ + f];
            m0 += kv * sw[i * 4 + 0];
            m1 += kv * sw[i * 4 + 1];
            m2 += kv * sw[i * 4 + 2];
            cc += kv * sw[i * 4 + 3];
        }
    }
    float4 r = make_float4(m0, m1, m2, cc);
    ((float4*)g_qkp8)[blockIdx.x * 256 + f] = r;
}

// ===========================================================================
// K1: single-pass attention pooling. 128 CTAs (one per batch), 1024 threads.
// 16 chunks of 64 rows, 3-deep cp.async pipeline, warp-0 register softmax.
// ===========================================================================
#define CHUNK_  64
#define ROWF_   256
#define NCH_    16

// shared memory layout (floats)
#define SB_BUF   0                          // 3 * 64*256 = 49152
#define SB_QK    49152                      // 256
#define SB_SC    (SB_QK + 256)              // 64
#define SB_PV    (SB_SC + 64)               // 64
#define SB_ST    (SB_PV + 64)               // 4  ([0]=alpha [1]=l)
#define SB_FRED  (SB_ST + 4)                // 16*256 = 4096
#define SB_TOTF  (SB_FRED + 4096)
#define K1_SMEM_BYTES (SB_TOTF * 4)         // 214,544 B

__device__ __forceinline__ void cp_async8(uint32_t saddr, const void* gaddr) {
    asm volatile("cp.async.ca.shared.global [%0], [%1], 8;" :: "r"(saddr), "l"(gaddr));
}

__global__ void __launch_bounds__(1024, 1)
attn_kernel(const float* __restrict__ input) {
    extern __shared__ float sm[];
    const int b   = blockIdx.x;
    const int tid = threadIdx.x;
    const uint32_t sb32 = (uint32_t)__cvta_generic_to_shared(sm);
    const float* gbase = input + (size_t)b * S_ * LAST_;

    // issue one 64-row chunk into buffer (c % 3); copies cols [0,256) per row
    auto issue = [&](int c) {
        const float* g = gbase + (size_t)c * CHUNK_ * LAST_;
        uint32_t s = sb32 + (uint32_t)((SB_BUF + (c % 3) * CHUNK_ * ROWF_) * 4);
#pragma unroll
        for (int j = 0; j < 8; j++) {
            int idx = tid + j * 1024;
            int r = idx >> 7, c2 = idx & 127;
            cp_async8(s + (uint32_t)((r * ROWF_ + c2 * 2) * 4), g + r * LAST_ + c2 * 2);
        }
        asm volatile("cp.async.commit_group;");
    };
    issue(0);
    issue(1);

    // prologue: qk vector = sum of 8 k0 partials, combined with this batch's archi
    const float a0 = gbase[FEAT_ + 0];
    const float a1 = gbase[FEAT_ + 1];
    const float a2 = gbase[FEAT_ + 2];
    if (tid < 256) {
        float4 s = make_float4(0.f, 0.f, 0.f, 0.f);
#pragma unroll
        for (int p = 0; p < 8; p++) {
            float4 v = ((const float4*)g_qkp8)[p * 256 + tid];
            s.x += v.x; s.y += v.y; s.z += v.z; s.w += v.w;
        }
        float val = (s.x * a0 + s.y * a1 + s.z * a2 + s.w) * rsqrtf(258.0f);
        if (tid >= FEAT_) val = 0.f;    // pad col (and archi cols) contribute 0
        sm[SB_QK + tid] = val;
    }
    __syncthreads();

    // score mapping: 16 threads per row; thread covers cols {j*64 + sub*4 ..+4}
    const int sub = tid & 15, row = tid >> 4;
    // fbar mapping: thread owns cols [c4*4, c4*4+4) over rows [grp*4, grp*4+4)
    const int c4 = tid & 63, grp = tid >> 6;

    float4 q[4];
#pragma unroll
    for (int j = 0; j < 4; j++)
        q[j] = *(const float4*)(sm + SB_QK + j * 64 + sub * 4);

    float m_run = -INFINITY, l_run = 0.f;   // live in warp 0 registers
    float4 acc = make_float4(0.f, 0.f, 0.f, 0.f);

    for (int c = 0; c < NCH_; c++) {
        if (c == NCH_ - 1) asm volatile("cp.async.wait_group 0;");
        else               asm volatile("cp.async.wait_group 1;");
        __syncthreads();                     // chunk c visible; prev buffers free
        if (c + 2 < NCH_) issue(c + 2);

        const float* cur = sm + SB_BUF + (c % 3) * CHUNK_ * ROWF_;

        // ---- scores (bank-conflict-free strided float4) ----
        {
            const float* rp = cur + row * ROWF_;
            float v = 0.f;
#pragma unroll
            for (int j = 0; j < 4; j++) {
                float4 x = *(const float4*)(rp + j * 64 + sub * 4);
                v += x.x * q[j].x + x.y * q[j].y + x.z * q[j].z + x.w * q[j].w;
            }
            v += __shfl_xor_sync(0xffffffffu, v, 1);
            v += __shfl_xor_sync(0xffffffffu, v, 2);
            v += __shfl_xor_sync(0xffffffffu, v, 4);
            v += __shfl_xor_sync(0xffffffffu, v, 8);
            if (sub == 0) sm[SB_SC + row] = v;
        }
        __syncthreads();

        // ---- warp-0 register softmax ----
        if (tid < 32) {
            float s0 = sm[SB_SC + tid], s1 = sm[SB_SC + 32 + tid];
            float mc = fmaxf(s0, s1);
#pragma unroll
            for (int o = 16; o; o >>= 1)
                mc = fmaxf(mc, __shfl_xor_sync(0xffffffffu, mc, o));
            float mnew  = fmaxf(m_run, mc);
            float alpha = __expf(m_run - mnew);
            float p0 = __expf(s0 - mnew), p1 = __expf(s1 - mnew);
            sm[SB_PV + tid] = p0;
            sm[SB_PV + 32 + tid] = p1;
            float ps = p0 + p1;
#pragma unroll
            for (int o = 16; o; o >>= 1)
                ps += __shfl_xor_sync(0xffffffffu, ps, o);
            l_run = l_run * alpha + ps;
            m_run = mnew;
            if (tid == 0) sm[SB_ST + 0] = alpha;
        }
        __syncthreads();

        // ---- fbar accumulation ----
        {
            float alpha = sm[SB_ST + 0];
            acc.x *= alpha; acc.y *= alpha; acc.z *= alpha; acc.w *= alpha;
            const float* fp = cur + c4 * 4;
#pragma unroll
            for (int j = 0; j < 4; j++) {
                float p = sm[SB_PV + grp * 4 + j];
                float4 x = *(const float4*)(fp + (grp * 4 + j) * ROWF_);
                acc.x += p * x.x; acc.y += p * x.y;
                acc.z += p * x.z; acc.w += p * x.w;
            }
        }
    }

    // ---- epilogue: reduce 16 group partials, normalize, write fbar^T ----
    *(float4*)(sm + SB_FRED + grp * 256 + c4 * 4) = acc;
    if (tid == 0) sm[SB_ST + 1] = l_run;
    __syncthreads();
    if (tid < FEAT_) {
        float s = 0.f;
#pragma unroll
        for (int g = 0; g < 16; g++) s += sm[SB_FRED + g * 256 + tid];
        g_fbarT[tid * 128 + b] = s / sm[SB_ST + 1];
    }
}

// ===========================================================================
// Split-K partial GEMM: P[ky][n][b] = sum_{k chunk} AT[k][b] * W[n][k]
// Tile 32n x 128b, block 256 (16 outputs/thread).
// ===========================================================================
__global__ void __launch_bounds__(256)
gemm_partial(const float* __restrict__ AT, const float* __restrict__ W,
             float* __restrict__ P, int K, int N, int KCH) {
    __shared__ float Wt[32 * 32];   // [kk][nn]
    const int tid  = threadIdx.x;
    const int b    = tid & 127;
    const int half = tid >> 7;
    const int n0   = blockIdx.x * 32;
    const int kbase = blockIdx.y * KCH;
    const int kend  = min(K, kbase + KCH);

    float acc[16];
#pragma unroll
    for (int i = 0; i < 16; i++) acc[i] = 0.f;

    for (int k0 = kbase; k0 < kend; k0 += 32) {
#pragma unroll
        for (int j = 0; j < 4; j++) {
            int e  = tid + j * 256;
            int nn = e >> 5, kk = e & 31;
            int k = k0 + kk, n = n0 + nn;
            Wt[kk * 32 + nn] = (k < kend && n < N) ? W[(size_t)n * K + k] : 0.f;
        }
        __syncthreads();
#pragma unroll
        for (int kk = 0; kk < 32; kk++) {
            float a = AT[(size_t)(k0 + kk) * 128 + b];   // pad rows are zero
            const float4* wr = (const float4*)&Wt[kk * 32 + half * 16];
            float4 w0 = wr[0], w1 = wr[1], w2 = wr[2], w3 = wr[3];
            acc[0]  += a * w0.x; acc[1]  += a * w0.y; acc[2]  += a * w0.z; acc[3]  += a * w0.w;
            acc[4]  += a * w1.x; acc[5]  += a * w1.y; acc[6]  += a * w1.z; acc[7]  += a * w1.w;
            acc[8]  += a * w2.x; acc[9]  += a * w2.y; acc[10] += a * w2.z; acc[11] += a * w2.w;
            acc[12] += a * w3.x; acc[13] += a * w3.y; acc[14] += a * w3.z; acc[15] += a * w3.w;
        }
        __syncthreads();
    }
#pragma unroll
    for (int i = 0; i < 16; i++) {
        int n = n0 + half * 16 + i;
        if (n < N) P[((size_t)blockIdx.y * N + n) * 128 + b] = acc[i];
    }
}

// ===========================================================================
// Reduce split-K partials + bias (+relu). Compile-time KS, float4 over b.
// grid = N/8, block 256: thread -> (n = e>>5, 4 consecutive b).
// ===========================================================================
template<int KS>
__global__ void __launch_bounds__(256)
reduce_bias_t(const float* __restrict__ P, const float* __restrict__ bias,
              float* __restrict__ outT, int N, int relu) {
    int e  = blockIdx.x * 256 + threadIdx.x;
    int n  = e >> 5;
    int b4 = (e & 31) * 4;
    float4 s = make_float4(0.f, 0.f, 0.f, 0.f);
#pragma unroll
    for (int ks = 0; ks < KS; ks++) {
        float4 v = *(const float4*)(P + ((size_t)ks * N + n) * 128 + b4);
        s.x += v.x; s.y += v.y; s.z += v.z; s.w += v.w;
    }
    float bb = bias[n];
    s.x += bb; s.y += bb; s.z += bb; s.w += bb;
    if (relu) {
        s.x = fmaxf(s.x, 0.f); s.y = fmaxf(s.y, 0.f);
        s.z = fmaxf(s.z, 0.f); s.w = fmaxf(s.w, 0.f);
    }
    *(float4*)(outT + (size_t)n * 128 + b4) = s;
}

// ===========================================================================
// Final layer: out[b][j] = h2[b] . W3[j] + b3[j]  (N=2, K=256). One CTA.
// ===========================================================================
__global__ void __launch_bounds__(512)
final_kernel(const float* __restrict__ h2T, const float* __restrict__ W3,
             const float* __restrict__ b3, float* __restrict__ out) {
    __shared__ float w3s[512];
    __shared__ float r0[4][128], r1[4][128];
    int tid = threadIdx.x;
    if (tid < 512) w3s[tid] = W3[tid];
    __syncthreads();
    int b = tid & 127, g = tid >> 7;
    float a0 = 0.f, a1 = 0.f;
#pragma unroll 8
    for (int j = 0; j < 64; j++) {
        int k = g * 64 + j;
        float a = h2T[(size_t)k * 128 + b];
        a0 += a * w3s[k];
        a1 += a * w3s[256 + k];
    }
    r0[g][b] = a0; r1[g][b] = a1;
    __syncthreads();
    if (tid < 128) {
        out[b * 2 + 0] = r0[0][b] + r0[1][b] + r0[2][b] + r0[3][b] + b3[0];
        out[b * 2 + 1] = r1[0][b] + r1[1][b] + r1[2][b] + r1[3][b] + b3[1];
    }
}

// ===========================================================================
extern "C" void kernel_launch(void* const* d_in, const int* in_sizes, int n_in,
                              void* d_out, int out_size) {
    const float* input = (const float*)d_in[0];
    const float* kW = (const float*)d_in[1];
    // d_in[2] = kb: constant score shift per batch -> cancels in softmax
    const float* vW = (const float*)d_in[3];
    const float* vb = (const float*)d_in[4];
    const float* qW = (const float*)d_in[5];
    const float* qb = (const float*)d_in[6];
    const float* W1 = (const float*)d_in[7];
    const float* b1 = (const float*)d_in[8];
    const float* W2 = (const float*)d_in[9];
    const float* b2 = (const float*)d_in[10];
    const float* W3 = (const float*)d_in[11];
    const float* b3 = (const float*)d_in[12];
    float* out = (float*)d_out;

    cudaFuncSetAttribute(attn_kernel, cudaFuncAttributeMaxDynamicSharedMemorySize,
                         K1_SMEM_BYTES);

    void *p_fbar, *p_res, *p_h1, *p_h2, *p_P;
    cudaGetSymbolAddress(&p_fbar, g_fbarT);
    cudaGetSymbolAddress(&p_res,  g_resT);
    cudaGetSymbolAddress(&p_h1,   g_h1T);
    cudaGetSymbolAddress(&p_h2,   g_h2T);
    cudaGetSymbolAddress(&p_P,    g_P);

    // qk projection params
    k0_kernel<<<8, 256>>>(kW, qW, qb);

    // attention pooling -> fbar^T (255 x 128)
    attn_kernel<<<128, 1024, K1_SMEM_BYTES>>>(input);

    // res = vW @ fbar + vb        (N=1024, K=255, split 2)
    gemm_partial<<<dim3(32, 2), 256>>>((const float*)p_fbar, vW, (float*)p_P, 255, 1024, 128);
    reduce_bias_t<2><<<128, 256>>>((const float*)p_P, vb, (float*)p_res, 1024, 0);

    // h1 = relu(W1 @ res + b1)    (N=512, K=1024, split 8)
    gemm_partial<<<dim3(16, 8), 256>>>((const float*)p_res, W1, (float*)p_P, 1024, 512, 128);
    reduce_bias_t<8><<<64, 256>>>((const float*)p_P, b1, (float*)p_h1, 512, 1);

    // h2 = relu(W2 @ h1 + b2)     (N=256, K=512, split 4)
    gemm_partial<<<dim3(8, 4), 256>>>((const float*)p_h1, W2, (float*)p_P, 512, 256, 128);
    reduce_bias_t<4><<<32, 256>>>((const float*)p_P, b2, (float*)p_h2, 256, 1);

    // out = W3 @ h2 + b3
    final_kernel<<<1, 512>>>((const float*)p_h2, W3, b3, out);
}

// round 4
// speedup vs baseline: 1.1060x; 1.1060x over previous
#include <cuda_runtime.h>
#include <cuda_bf16.h>
#include <cstdint>
#include <math.h>

// ---------------------------------------------------------------------------
// SimpleModelQ collapsed:
//   qk[b] = (M @ archi[b] + c) / sqrt(258),  M = kW^T qW, c = kW^T qb
//   (q.kb score shift is constant per batch -> cancels in softmax)
//   fbar[b] = softmax(qk[b].feats[b,s])-weighted mean of feats (255-dim)
//   res = vW@fbar+vb; h1=relu(W1@res+b1); h2=relu(W2@h1+b2); out=W3@h2+b3
// ---------------------------------------------------------------------------

#define B_     128
#define S_     1024
#define LAST_  258
#define FEAT_  255

// ---- device scratch (zero-init at load; rows beyond FEAT_ stay zero) ----
__device__ float g_qkp8[8 * 256 * 4];   // k0 partials [blk][f][{M0,M1,M2,c}]
__device__ float g_fbarT[256 * 128];    // k-major [f][b]; row 255 stays 0 (pad)
__device__ float g_resT[1024 * 128];
__device__ float g_h1T[512 * 128];
__device__ float g_P[8192 * 128];       // split-K partials

// ===========================================================================
// K0: partial M/c over a 128-h chunk. grid 8, block 256 (thread = feature f).
// ===========================================================================
__global__ void __launch_bounds__(256)
k0_kernel(const float* __restrict__ kW, const float* __restrict__ qW,
          const float* __restrict__ qb) {
    __shared__ float sw[128 * 4];
    const int f = threadIdx.x;
    const int h0 = blockIdx.x * 128;
    for (int j = f; j < 512; j += 256) {
        int h = h0 + (j >> 2), k = j & 3;
        sw[j] = (k < 3) ? qW[h * 3 + k] : qb[h];
    }
    __syncthreads();
    float m0 = 0.f, m1 = 0.f, m2 = 0.f, cc = 0.f;
    if (f < FEAT_) {
#pragma unroll 4
        for (int i = 0; i < 128; i++) {
            float kv = kW[(size_t)(h0 + i) * FEAT_ + f];
            m0 += kv * sw[i * 4 + 0];
            m1 += kv * sw[i * 4 + 1];
            m2 += kv * sw[i * 4 + 2];
            cc += kv * sw[i * 4 + 3];
        }
    }
    ((float4*)g_qkp8)[blockIdx.x * 256 + f] = make_float4(m0, m1, m2, cc);
}

// ===========================================================================
// K1: attention pooling with cp.async.bulk chunk loads (full 258-f rows,
// so all smem row accesses are float2 / 8B-aligned). 128 CTAs x 1024 thr,
// 16 chunks x 64 rows, 3-stage mbarrier ring, warp-0 register softmax.
// ===========================================================================
#define CHUNK_  64
#define NCH_    16
#define CHUNK_BYTES (CHUNK_ * LAST_ * 4)    // 66048, multiple of 16

// shared layout (floats)
#define SB_BUF   0                          // 3 * 64*258 = 49536
#define SB_QK    49536                      // 256
#define SB_SC    (SB_QK + 256)              // 64
#define SB_PV    (SB_SC + 64)               // 64
#define SB_ST    (SB_PV + 64)               // 4  ([0]=alpha [1]=l)
#define SB_MB    (SB_ST + 4)                // 8  (3 x u64 mbarriers; byte off %8==0)
#define SB_FRED  (SB_MB + 8)                // 8*256 = 2048
#define SB_TOTF  (SB_FRED + 2048)
#define K1_SMEM_BYTES (SB_TOTF * 4)         // 207,920 B

__global__ void __launch_bounds__(1024, 1)
attn_kernel(const float* __restrict__ input) {
    extern __shared__ float sm[];
    const int b   = blockIdx.x;
    const int tid = threadIdx.x;
    const uint32_t sb32 = (uint32_t)__cvta_generic_to_shared(sm);
    const uint32_t mb   = sb32 + SB_MB * 4;
    const float* gbase = input + (size_t)b * S_ * LAST_;

    if (tid == 0) {
#pragma unroll
        for (int s = 0; s < 3; s++)
            asm volatile("mbarrier.init.shared.b64 [%0], 1;" :: "r"(mb + s * 8) : "memory");
    }
    __syncthreads();

    auto issue = [&](int c) {
        if (tid == 0) {
            uint32_t bar = mb + (c % 3) * 8;
            uint32_t dst = sb32 + (uint32_t)((SB_BUF + (c % 3) * CHUNK_ * LAST_) * 4);
            const float* g = gbase + (size_t)c * CHUNK_ * LAST_;
            asm volatile("mbarrier.arrive.expect_tx.shared.b64 _, [%0], %1;"
                         :: "r"(bar), "r"((uint32_t)CHUNK_BYTES) : "memory");
            asm volatile("cp.async.bulk.shared::cta.global.mbarrier::complete_tx::bytes "
                         "[%0], [%1], %2, [%3];"
                         :: "r"(dst), "l"(g), "r"((uint32_t)CHUNK_BYTES), "r"(bar)
                         : "memory");
        }
    };
    issue(0);
    issue(1);

    // prologue: qk vector
    const float a0 = gbase[FEAT_ + 0];
    const float a1 = gbase[FEAT_ + 1];
    const float a2 = gbase[FEAT_ + 2];
    if (tid < 256) {
        float4 s = make_float4(0.f, 0.f, 0.f, 0.f);
#pragma unroll
        for (int p = 0; p < 8; p++) {
            float4 v = ((const float4*)g_qkp8)[p * 256 + tid];
            s.x += v.x; s.y += v.y; s.z += v.z; s.w += v.w;
        }
        float val = (s.x * a0 + s.y * a1 + s.z * a2 + s.w) * rsqrtf(258.0f);
        if (tid >= FEAT_) val = 0.f;   // masks pad col 255
        sm[SB_QK + tid] = val;
    }
    __syncthreads();

    const int sub = tid & 15, row = tid >> 4;    // scores: 16 thr/row
    const int c2  = tid & 127, grp = tid >> 7;   // fbar: col-pair x 8-row group

    // qk register cache: thread sub covers cols {j*32 + sub*2, +1}, j=0..7
    float2 q2[8];
#pragma unroll
    for (int j = 0; j < 8; j++)
        q2[j] = *(const float2*)(sm + SB_QK + j * 32 + sub * 2);

    float m_run = -INFINITY, l_run = 0.f;
    float2 acc = make_float2(0.f, 0.f);

    for (int c = 0; c < NCH_; c++) {
        // wait chunk c
        {
            uint32_t bar = mb + (c % 3) * 8;
            uint32_t ph = (uint32_t)((c / 3) & 1);
            uint32_t done;
            asm volatile("{\n\t.reg .pred p;\n\t"
                         "mbarrier.try_wait.parity.acquire.cta.shared::cta.b64 p, [%1], %2;\n\t"
                         "selp.b32 %0, 1, 0, p;\n\t}"
                         : "=r"(done) : "r"(bar), "r"(ph) : "memory");
            if (!done) {
                asm volatile("{\n\t.reg .pred P1;\n\t"
                             "WL_%=:\n\t"
                             "mbarrier.try_wait.parity.acquire.cta.shared::cta.b64 P1, [%0], %1, 0x989680;\n\t"
                             "@P1 bra.uni WD_%=;\n\t"
                             "bra.uni WL_%=;\n\t"
                             "WD_%=:\n\t}"
                             :: "r"(bar), "r"(ph) : "memory");
            }
        }
        // buffer (c+2)%3 was drained by end-of-(c-1) __syncthreads
        if (c + 2 < NCH_) issue(c + 2);

        const float* cur = sm + SB_BUF + (c % 3) * CHUNK_ * LAST_;

        // ---- scores (float2, stride-32 across j: conflict-free) ----
        {
            const float* rp = cur + row * LAST_;
            float v = 0.f;
#pragma unroll
            for (int j = 0; j < 8; j++) {
                float2 x = *(const float2*)(rp + j * 32 + sub * 2);
                v += x.x * q2[j].x + x.y * q2[j].y;
            }
            v += __shfl_xor_sync(0xffffffffu, v, 1);
            v += __shfl_xor_sync(0xffffffffu, v, 2);
            v += __shfl_xor_sync(0xffffffffu, v, 4);
            v += __shfl_xor_sync(0xffffffffu, v, 8);
            if (sub == 0) sm[SB_SC + row] = v;
        }
        __syncthreads();

        // ---- warp-0 register softmax ----
        if (tid < 32) {
            float s0 = sm[SB_SC + tid], s1 = sm[SB_SC + 32 + tid];
            float mc = fmaxf(s0, s1);
#pragma unroll
            for (int o = 16; o; o >>= 1)
                mc = fmaxf(mc, __shfl_xor_sync(0xffffffffu, mc, o));
            float mnew  = fmaxf(m_run, mc);
            float alpha = __expf(m_run - mnew);
            float p0 = __expf(s0 - mnew), p1 = __expf(s1 - mnew);
            sm[SB_PV + tid] = p0;
            sm[SB_PV + 32 + tid] = p1;
            float ps = p0 + p1;
#pragma unroll
            for (int o = 16; o; o >>= 1)
                ps += __shfl_xor_sync(0xffffffffu, ps, o);
            l_run = l_run * alpha + ps;
            m_run = mnew;
            if (tid == 0) sm[SB_ST + 0] = alpha;
        }
        __syncthreads();

        // ---- fbar accumulation (float2; col-pair 127 = pad, discarded) ----
        {
            float alpha = sm[SB_ST + 0];
            acc.x *= alpha; acc.y *= alpha;
            const float* fp = cur + c2 * 2;
#pragma unroll
            for (int j = 0; j < 8; j++) {
                float p = sm[SB_PV + grp * 8 + j];
                float2 x = *(const float2*)(fp + (grp * 8 + j) * LAST_);
                acc.x += p * x.x; acc.y += p * x.y;
            }
        }
        __syncthreads();   // PV/SC reuse + buffer-free guarantee for issue()
    }

    // ---- epilogue: reduce 8 group partials, normalize, write fbar^T ----
    *(float2*)(sm + SB_FRED + grp * 256 + c2 * 2) = acc;
    if (tid == 0) sm[SB_ST + 1] = l_run;
    __syncthreads();
    if (tid < FEAT_) {
        float s = 0.f;
#pragma unroll
        for (int g = 0; g < 8; g++) s += sm[SB_FRED + g * 256 + tid];
        g_fbarT[tid * 128 + b] = s / sm[SB_ST + 1];
    }
}

// ===========================================================================
// Split-K partial GEMM with packed f32x2 FMA.
// P[ky][n][b] = sum_{k chunk} AT[k][b] * W[n][k].  Tile 32n x 128b, 256 thr.
// ===========================================================================
__global__ void __launch_bounds__(256)
gemm_partial(const float* __restrict__ AT, const float* __restrict__ W,
             float* __restrict__ P, int K, int N, int KCH) {
    __shared__ __align__(16) float Wt[32 * 32];   // [kk][nn]
    const int tid  = threadIdx.x;
    const int b    = tid & 127;
    const int half = tid >> 7;
    const int n0   = blockIdx.x * 32;
    const int kbase = blockIdx.y * KCH;
    const int kend  = min(K, kbase + KCH);

    unsigned long long acc2[8];
#pragma unroll
    for (int i = 0; i < 8; i++) acc2[i] = 0ull;

    for (int k0 = kbase; k0 < kend; k0 += 32) {
#pragma unroll
        for (int j = 0; j < 4; j++) {
            int e  = tid + j * 256;
            int nn = e >> 5, kk = e & 31;
            int k = k0 + kk, n = n0 + nn;
            Wt[kk * 32 + nn] = (k < kend && n < N) ? W[(size_t)n * K + k] : 0.f;
        }
        __syncthreads();
#pragma unroll
        for (int kk = 0; kk < 32; kk++) {
            float a = AT[(size_t)(k0 + kk) * 128 + b];   // pad rows are zero
            unsigned long long ap;
            asm("mov.b64 %0, {%1, %1};" : "=l"(ap) : "f"(a));
            const unsigned long long* wr =
                (const unsigned long long*)&Wt[kk * 32 + half * 16];
#pragma unroll
            for (int i = 0; i < 8; i++)
                asm("fma.rn.f32x2 %0, %1, %2, %0;" : "+l"(acc2[i]) : "l"(ap), "l"(wr[i]));
        }
        __syncthreads();
    }
#pragma unroll
    for (int i = 0; i < 8; i++) {
        float lo, hi;
        asm("mov.b64 {%0, %1}, %2;" : "=f"(lo), "=f"(hi) : "l"(acc2[i]));
        int n = n0 + half * 16 + 2 * i;
        if (n < N)     P[((size_t)blockIdx.y * N + n) * 128 + b] = lo;
        if (n + 1 < N) P[((size_t)blockIdx.y * N + n + 1) * 128 + b] = hi;
    }
}

// ===========================================================================
// Reduce split-K partials + bias (+relu). Compile-time KS, float4 over b.
// ===========================================================================
template<int KS>
__global__ void __launch_bounds__(256)
reduce_bias_t(const float* __restrict__ P, const float* __restrict__ bias,
              float* __restrict__ outT, int N, int relu) {
    int e  = blockIdx.x * 256 + threadIdx.x;
    int n  = e >> 5;
    int b4 = (e & 31) * 4;
    float4 s = make_float4(0.f, 0.f, 0.f, 0.f);
#pragma unroll
    for (int ks = 0; ks < KS; ks++) {
        float4 v = *(const float4*)(P + ((size_t)ks * N + n) * 128 + b4);
        s.x += v.x; s.y += v.y; s.z += v.z; s.w += v.w;
    }
    float bb = bias[n];
    s.x += bb; s.y += bb; s.z += bb; s.w += bb;
    if (relu) {
        s.x = fmaxf(s.x, 0.f); s.y = fmaxf(s.y, 0.f);
        s.z = fmaxf(s.z, 0.f); s.w = fmaxf(s.w, 0.f);
    }
    *(float4*)(outT + (size_t)n * 128 + b4) = s;
}

// ===========================================================================
// Tail: h2 = relu(sum_ks P + b2) kept in smem (stride 132), then W3 matvec.
// One CTA, 1024 threads.
// ===========================================================================
#define TL_H2   0
#define TL_W3   (256 * 132)
#define TL_R0   (TL_W3 + 512)
#define TL_R1   (TL_R0 + 8 * 128)
#define TL_TOTF (TL_R1 + 8 * 128)
#define TL_SMEM_BYTES (TL_TOTF * 4)

__global__ void __launch_bounds__(1024)
tail_kernel(const float* __restrict__ P, const float* __restrict__ b2,
            const float* __restrict__ W3, const float* __restrict__ b3,
            float* __restrict__ out) {
    extern __shared__ float ts[];
    const int tid = threadIdx.x;

    // phase 1: h2[n][b] = relu(sum_{ks<4} P[ks][n][b] + b2[n]) into smem
#pragma unroll
    for (int j = 0; j < 8; j++) {
        int idx = tid + j * 1024;
        int n = idx >> 5, b4 = (idx & 31) * 4;
        float4 s = make_float4(0.f, 0.f, 0.f, 0.f);
#pragma unroll
        for (int ks = 0; ks < 4; ks++) {
            float4 v = *(const float4*)(P + ((size_t)ks * 256 + n) * 128 + b4);
            s.x += v.x; s.y += v.y; s.z += v.z; s.w += v.w;
        }
        float bb = b2[n];
        s.x = fmaxf(s.x + bb, 0.f); s.y = fmaxf(s.y + bb, 0.f);
        s.z = fmaxf(s.z + bb, 0.f); s.w = fmaxf(s.w + bb, 0.f);
        *(float4*)(ts + TL_H2 + n * 132 + b4) = s;
    }
    if (tid < 512) ts[TL_W3 + tid] = W3[tid];
    __syncthreads();

    // phase 2: out[b] = W3 @ h2[:, b] + b3
    const int b = tid & 127, g = tid >> 7;    // 8 groups of 32 k
    float s0 = 0.f, s1 = 0.f;
#pragma unroll
    for (int j = 0; j < 32; j++) {
        int k = g * 32 + j;
        float a = ts[TL_H2 + k * 132 + b];
        s0 += a * ts[TL_W3 + k];
        s1 += a * ts[TL_W3 + 256 + k];
    }
    ts[TL_R0 + g * 128 + b] = s0;
    ts[TL_R1 + g * 128 + b] = s1;
    __syncthreads();
    if (tid < 128) {
        float o0 = b3[0], o1 = b3[1];
#pragma unroll
        for (int g2 = 0; g2 < 8; g2++) {
            o0 += ts[TL_R0 + g2 * 128 + tid];
            o1 += ts[TL_R1 + g2 * 128 + tid];
        }
        out[tid * 2 + 0] = o0;
        out[tid * 2 + 1] = o1;
    }
}

// ===========================================================================
extern "C" void kernel_launch(void* const* d_in, const int* in_sizes, int n_in,
                              void* d_out, int out_size) {
    const float* input = (const float*)d_in[0];
    const float* kW = (const float*)d_in[1];
    // d_in[2] = kb: constant score shift per batch -> cancels in softmax
    const float* vW = (const float*)d_in[3];
    const float* vb = (const float*)d_in[4];
    const float* qW = (const float*)d_in[5];
    const float* qb = (const float*)d_in[6];
    const float* W1 = (const float*)d_in[7];
    const float* b1 = (const float*)d_in[8];
    const float* W2 = (const float*)d_in[9];
    const float* b2 = (const float*)d_in[10];
    const float* W3 = (const float*)d_in[11];
    const float* b3 = (const float*)d_in[12];
    float* out = (float*)d_out;

    cudaFuncSetAttribute(attn_kernel, cudaFuncAttributeMaxDynamicSharedMemorySize,
                         K1_SMEM_BYTES);
    cudaFuncSetAttribute(tail_kernel, cudaFuncAttributeMaxDynamicSharedMemorySize,
                         TL_SMEM_BYTES);

    void *p_fbar, *p_res, *p_h1, *p_P;
    cudaGetSymbolAddress(&p_fbar, g_fbarT);
    cudaGetSymbolAddress(&p_res,  g_resT);
    cudaGetSymbolAddress(&p_h1,   g_h1T);
    cudaGetSymbolAddress(&p_P,    g_P);

    // qk projection params
    k0_kernel<<<8, 256>>>(kW, qW, qb);

    // attention pooling -> fbar^T (255 x 128)
    attn_kernel<<<128, 1024, K1_SMEM_BYTES>>>(input);

    // res = vW @ fbar + vb        (N=1024, K=255, split 2)
    gemm_partial<<<dim3(32, 2), 256>>>((const float*)p_fbar, vW, (float*)p_P, 255, 1024, 128);
    reduce_bias_t<2><<<128, 256>>>((const float*)p_P, vb, (float*)p_res, 1024, 0);

    // h1 = relu(W1 @ res + b1)    (N=512, K=1024, split 8)
    gemm_partial<<<dim3(16, 8), 256>>>((const float*)p_res, W1, (float*)p_P, 1024, 512, 128);
    reduce_bias_t<8><<<64, 256>>>((const float*)p_P, b1, (float*)p_h1, 512, 1);

    // h2 partials (N=256, K=512, split 4); tail fuses reduce+bias+relu+W3
    gemm_partial<<<dim3(8, 4), 256>>>((const float*)p_h1, W2, (float*)p_P, 512, 256, 128);
    tail_kernel<<<1, 1024, TL_SMEM_BYTES>>>((const float*)p_P, b2, W3, b3, out);
}